// round 3
// baseline (speedup 1.0000x reference)
#include <cuda_runtime.h>
#include <math_constants.h>

// B=4, N=M=4096, D=3; scalar fp32 output
#define BATCH   4
#define NPTS    4096
#define TPB     128
#define RQ      4                        // queries per thread
#define QPB     (TPB * RQ)               // 512 queries per block
#define QCHUNKS (NPTS / QPB)             // 8
#define SSPLIT  32                       // target-range splits
#define TILE_T  (NPTS / SSPLIT)          // 128 targets per block
#define NBLOCKS (2 * BATCH * QCHUNKS * SSPLIT)   // 2048
#define NQ_TOT  (2 * BATCH * NPTS)       // 32768 query jobs
#define CBLOCKS 128
#define CTPB    256

// Per-query-job min, ordered-uint encoded (max-of-uint == min-of-float).
// Zero-init == "worst" value; combine resets to 0 after reading (graph replay).
__device__ unsigned int g_minenc[NQ_TOT];   // 128 KB
__device__ float g_bsum[CBLOCKS];
__device__ unsigned int g_count;

typedef unsigned long long ull;

__device__ __forceinline__ unsigned enc_min(float f) {
    unsigned b = __float_as_uint(f);
    unsigned m = (b & 0x80000000u) ? ~b : (b | 0x80000000u);  // monotone inc in f
    return ~m;                                                // monotone dec; >0 for finite f
}
__device__ __forceinline__ float dec_min(unsigned k) {
    unsigned m = ~k;
    unsigned b = (m & 0x80000000u) ? (m ^ 0x80000000u) : ~m;
    return __uint_as_float(b);
}

__device__ __forceinline__ ull pack2(float v) {
    ull r;
    asm("mov.b64 %0, {%1, %1};" : "=l"(r) : "f"(v));
    return r;
}
__device__ __forceinline__ ull fma2(ull a, ull b, ull c) {
    ull d;
    asm("fma.rn.f32x2 %0, %1, %2, %3;" : "=l"(d) : "l"(a), "l"(b), "l"(c));
    return d;
}
__device__ __forceinline__ void min2(float& m0, float& m1, ull s) {
    float lo, hi;
    asm("mov.b64 {%0, %1}, %2;" : "=f"(lo), "=f"(hi) : "l"(s));
    m0 = fminf(m0, lo);
    m1 = fminf(m1, hi);
}

__global__ __launch_bounds__(TPB)
void chamfer_partial_kernel(const float* __restrict__ X, const float* __restrict__ Y) {
    const int bid = blockIdx.x;
    const int s   = bid & (SSPLIT - 1);
    const int qc  = (bid >> 5) & (QCHUNKS - 1);
    const int b   = (bid >> 8) & (BATCH - 1);
    const int dir = bid >> 10;

    const float* __restrict__ Q = dir ? Y : X;
    const float* __restrict__ T = dir ? X : Y;

    __shared__ __align__(16) float sx0[TILE_T];
    __shared__ __align__(16) float sx1[TILE_T];
    __shared__ __align__(16) float sx2[TILE_T];
    __shared__ __align__(16) float swv[TILE_T];

    // Target tile (SoA): coords + 0.5*||t||^2
    const int tb = s * TILE_T;
    if (threadIdx.x < TILE_T) {
        const int t = threadIdx.x;
        const float* tp = T + ((size_t)b * NPTS + tb + t) * 3;
        const float a0 = tp[0], a1 = tp[1], a2 = tp[2];
        sx0[t] = a0; sx1[t] = a1; sx2[t] = a2;
        swv[t] = 0.5f * (a0 * a0 + a1 * a1 + a2 * a2);
    }

    // Per-thread queries (negated, packed)
    const int q0 = qc * QPB + threadIdx.x;
    ull nx[RQ], ny[RQ], nz[RQ];
    #pragma unroll
    for (int r = 0; r < RQ; r++) {
        const int q = q0 + r * TPB;
        const float* qp = Q + ((size_t)b * NPTS + q) * 3;
        nx[r] = pack2(-qp[0]); ny[r] = pack2(-qp[1]); nz[r] = pack2(-qp[2]);
    }
    __syncthreads();

    float m0[RQ], m1[RQ];
    #pragma unroll
    for (int r = 0; r < RQ; r++) { m0[r] = CUDART_INF_F; m1[r] = CUDART_INF_F; }

    const ulonglong2* px = (const ulonglong2*)sx0;
    const ulonglong2* py = (const ulonglong2*)sx1;
    const ulonglong2* pz = (const ulonglong2*)sx2;
    const ulonglong2* pw = (const ulonglong2*)swv;

    #pragma unroll 4
    for (int g = 0; g < TILE_T / 4; g++) {
        const ulonglong2 Xv = px[g];
        const ulonglong2 Yv = py[g];
        const ulonglong2 Zv = pz[g];
        const ulonglong2 Wv = pw[g];
        #pragma unroll
        for (int r = 0; r < RQ; r++) {
            // s = 0.5||t||^2 - q.t  (two targets per packed op)
            const ull s01 = fma2(nx[r], Xv.x, fma2(ny[r], Yv.x, fma2(nz[r], Zv.x, Wv.x)));
            const ull s23 = fma2(nx[r], Xv.y, fma2(ny[r], Yv.y, fma2(nz[r], Zv.y, Wv.y)));
            min2(m0[r], m1[r], s01);
            min2(m0[r], m1[r], s23);
        }
    }

    // One REDG-style atomicMax per query job (min-of-float via encoded max)
    #pragma unroll
    for (int r = 0; r < RQ; r++) {
        const int q = q0 + r * TPB;
        const int item = (dir * BATCH + b) * NPTS + q;
        atomicMax(&g_minenc[item], enc_min(fminf(m0[r], m1[r])));
    }
}

__global__ __launch_bounds__(CTPB)
void chamfer_combine_kernel(const float* __restrict__ X, const float* __restrict__ Y,
                            float* __restrict__ out) {
    const int item = blockIdx.x * CTPB + threadIdx.x;   // blocks [0,64)=dir0, [64,128)=dir1
    const int dir  = item >> 14;
    const int rem  = item & 16383;
    const int b    = rem >> 12;
    const int q    = rem & 4095;

    const float* __restrict__ Q = dir ? Y : X;
    const float* qp = Q + ((size_t)b * NPTS + q) * 3;
    const float a = qp[0], c = qp[1], d = qp[2];
    const float qn = a * a + c * c + d * d;

    const float m = dec_min(__ldcg(&g_minenc[item]));
    g_minenc[item] = 0u;                        // reset for next graph replay
    float d2 = fmaxf(fmaf(2.0f, m, qn), 0.0f);

    __shared__ float wsum[CTPB / 32];
    #pragma unroll
    for (int o = 16; o > 0; o >>= 1)
        d2 += __shfl_xor_sync(0xFFFFFFFFu, d2, o);
    const int wid  = threadIdx.x >> 5;
    const int lane = threadIdx.x & 31;
    if (lane == 0) wsum[wid] = d2;
    __syncthreads();

    __shared__ unsigned int ticket;
    if (threadIdx.x == 0) {
        float ssum = 0.0f;
        #pragma unroll
        for (int w = 0; w < CTPB / 32; w++) ssum += wsum[w];
        g_bsum[blockIdx.x] = ssum;
        __threadfence();
        ticket = atomicAdd(&g_count, 1u);
    }
    __syncthreads();

    if (ticket == CBLOCKS - 1) {
        if (threadIdx.x == 0) {
            float s0 = 0.0f, s1 = 0.0f;
            for (int i = 0; i < CBLOCKS / 2; i++)       s0 += __ldcg(&g_bsum[i]);
            for (int i = CBLOCKS / 2; i < CBLOCKS; i++) s1 += __ldcg(&g_bsum[i]);
            out[0] = fmaxf(s0, s1) * (1.0f / (float)(BATCH * NPTS));
            g_count = 0;
        }
    }
}

extern "C" void kernel_launch(void* const* d_in, const int* in_sizes, int n_in,
                              void* d_out, int out_size) {
    const float* x = (const float*)d_in[0];
    const float* y = (const float*)d_in[1];
    float* out = (float*)d_out;

    chamfer_partial_kernel<<<NBLOCKS, TPB>>>(x, y);
    chamfer_combine_kernel<<<CBLOCKS, CTPB>>>(x, y, out);
}

// round 4
// speedup vs baseline: 1.3498x; 1.3498x over previous
#include <cuda_runtime.h>
#include <math_constants.h>

// B=4, N=M=4096, D=3; scalar fp32 output
#define BATCH   4
#define NPTS    4096
#define TPB     128
#define RQ      4                        // queries per thread
#define QPB     (TPB * RQ)               // 512 queries per block
#define QCHUNKS (NPTS / QPB)             // 8
#define SSPLIT  8                        // target-range splits
#define TILE_T  (NPTS / SSPLIT)          // 512 targets per block
#define NBLOCKS (2 * BATCH * QCHUNKS * SSPLIT)   // 512
#define NQ_TOT  (2 * BATCH * NPTS)       // 32768 query jobs
#define CBLOCKS 256
#define CTPB    128

// Scratch: partial min (of s = 0.5||t||^2 - q.t) per (query-job, split)
__device__ float g_partial[NQ_TOT * SSPLIT];   // 1 MB, fully overwritten each replay
__device__ float g_bsum[CBLOCKS];
__device__ unsigned int g_count;               // zero-init; reset by last block

typedef unsigned long long ull;

__device__ __forceinline__ ull pack2(float v) {
    ull r;
    asm("mov.b64 %0, {%1, %1};" : "=l"(r) : "f"(v));
    return r;
}
__device__ __forceinline__ ull fma2(ull a, ull b, ull c) {
    ull d;
    asm("fma.rn.f32x2 %0, %1, %2, %3;" : "=l"(d) : "l"(a), "l"(b), "l"(c));
    return d;
}
__device__ __forceinline__ void min2(float& m0, float& m1, ull s) {
    float lo, hi;
    asm("mov.b64 {%0, %1}, %2;" : "=f"(lo), "=f"(hi) : "l"(s));
    m0 = fminf(m0, lo);
    m1 = fminf(m1, hi);
}

__global__ __launch_bounds__(TPB)
void chamfer_partial_kernel(const float* __restrict__ X, const float* __restrict__ Y) {
    const int bid = blockIdx.x;
    const int s   = bid & (SSPLIT - 1);          // bits 0-2
    const int qc  = (bid >> 3) & (QCHUNKS - 1);  // bits 3-5
    const int b   = (bid >> 6) & (BATCH - 1);    // bits 6-7
    const int dir = bid >> 8;                    // bit 8

    const float* __restrict__ Q = dir ? Y : X;
    const float* __restrict__ T = dir ? X : Y;

    __shared__ __align__(16) float sx0[TILE_T];
    __shared__ __align__(16) float sx1[TILE_T];
    __shared__ __align__(16) float sx2[TILE_T];
    __shared__ __align__(16) float swv[TILE_T];

    // Target tile (SoA): coords + 0.5*||t||^2
    const int tb = s * TILE_T;
    for (int t = threadIdx.x; t < TILE_T; t += TPB) {
        const float* tp = T + ((size_t)b * NPTS + tb + t) * 3;
        const float a0 = tp[0], a1 = tp[1], a2 = tp[2];
        sx0[t] = a0; sx1[t] = a1; sx2[t] = a2;
        swv[t] = 0.5f * (a0 * a0 + a1 * a1 + a2 * a2);
    }

    // Per-thread queries (negated, packed)
    const int q0 = qc * QPB + threadIdx.x;
    ull nx[RQ], ny[RQ], nz[RQ];
    #pragma unroll
    for (int r = 0; r < RQ; r++) {
        const int q = q0 + r * TPB;
        const float* qp = Q + ((size_t)b * NPTS + q) * 3;
        nx[r] = pack2(-qp[0]); ny[r] = pack2(-qp[1]); nz[r] = pack2(-qp[2]);
    }
    __syncthreads();

    float m0[RQ], m1[RQ];
    #pragma unroll
    for (int r = 0; r < RQ; r++) { m0[r] = CUDART_INF_F; m1[r] = CUDART_INF_F; }

    const ulonglong2* px = (const ulonglong2*)sx0;
    const ulonglong2* py = (const ulonglong2*)sx1;
    const ulonglong2* pz = (const ulonglong2*)sx2;
    const ulonglong2* pw = (const ulonglong2*)swv;

    #pragma unroll 2
    for (int g = 0; g < TILE_T / 4; g++) {
        const ulonglong2 Xv = px[g];
        const ulonglong2 Yv = py[g];
        const ulonglong2 Zv = pz[g];
        const ulonglong2 Wv = pw[g];
        #pragma unroll
        for (int r = 0; r < RQ; r++) {
            // s = 0.5||t||^2 - q.t  (two targets per packed op)
            const ull s01 = fma2(nx[r], Xv.x, fma2(ny[r], Yv.x, fma2(nz[r], Zv.x, Wv.x)));
            const ull s23 = fma2(nx[r], Xv.y, fma2(ny[r], Yv.y, fma2(nz[r], Zv.y, Wv.y)));
            min2(m0[r], m1[r], s01);
            min2(m0[r], m1[r], s23);
        }
    }

    // Plain scratch store (no atomics)
    #pragma unroll
    for (int r = 0; r < RQ; r++) {
        const int q = q0 + r * TPB;
        const int item = (dir * BATCH + b) * NPTS + q;
        g_partial[item * SSPLIT + s] = fminf(m0[r], m1[r]);
    }
}

__global__ __launch_bounds__(CTPB)
void chamfer_combine_kernel(const float* __restrict__ X, const float* __restrict__ Y,
                            float* __restrict__ out) {
    const int item = blockIdx.x * CTPB + threadIdx.x;   // 256*128 = 32768 exactly
    const int dir  = item >> 14;                        // blocks [0,128)=dir0, [128,256)=dir1
    const int rem  = item & 16383;
    const int b    = rem >> 12;
    const int q    = rem & 4095;

    const float* __restrict__ Q = dir ? Y : X;
    const float* qp = Q + ((size_t)b * NPTS + q) * 3;
    const float a = qp[0], c = qp[1], d = qp[2];
    const float qn = a * a + c * c + d * d;

    // Min over the SSPLIT=8 partials (two independent LDG.128)
    const float4* pr = (const float4*)(g_partial + (size_t)item * SSPLIT);
    const float4 v0 = pr[0];
    const float4 v1 = pr[1];
    const float m = fminf(fminf(fminf(v0.x, v0.y), fminf(v0.z, v0.w)),
                          fminf(fminf(v1.x, v1.y), fminf(v1.z, v1.w)));
    float d2 = fmaxf(fmaf(2.0f, m, qn), 0.0f);

    // Deterministic block sum
    __shared__ float wsum[CTPB / 32];
    #pragma unroll
    for (int o = 16; o > 0; o >>= 1)
        d2 += __shfl_xor_sync(0xFFFFFFFFu, d2, o);
    const int wid  = threadIdx.x >> 5;
    const int lane = threadIdx.x & 31;
    if (lane == 0) wsum[wid] = d2;
    __syncthreads();

    __shared__ unsigned int ticket;
    if (threadIdx.x == 0) {
        float ssum = 0.0f;
        #pragma unroll
        for (int w = 0; w < CTPB / 32; w++) ssum += wsum[w];
        g_bsum[blockIdx.x] = ssum;
        __threadfence();
        ticket = atomicAdd(&g_count, 1u);
    }
    __syncthreads();

    if (ticket == CBLOCKS - 1) {
        // Last block finalizes with all 128 threads: bsum[0:128)=dir0, [128:256)=dir1
        float s0 = __ldcg(&g_bsum[threadIdx.x]);
        float s1 = __ldcg(&g_bsum[CTPB + threadIdx.x]);
        #pragma unroll
        for (int o = 16; o > 0; o >>= 1) {
            s0 += __shfl_xor_sync(0xFFFFFFFFu, s0, o);
            s1 += __shfl_xor_sync(0xFFFFFFFFu, s1, o);
        }
        __shared__ float f0[CTPB / 32], f1[CTPB / 32];
        if (lane == 0) { f0[wid] = s0; f1[wid] = s1; }
        __syncthreads();
        if (threadIdx.x == 0) {
            float a0 = 0.0f, a1 = 0.0f;
            #pragma unroll
            for (int w = 0; w < CTPB / 32; w++) { a0 += f0[w]; a1 += f1[w]; }
            out[0] = fmaxf(a0, a1) * (1.0f / (float)(BATCH * NPTS));
            g_count = 0;   // reset for next graph replay
        }
    }
}

extern "C" void kernel_launch(void* const* d_in, const int* in_sizes, int n_in,
                              void* d_out, int out_size) {
    const float* x = (const float*)d_in[0];
    const float* y = (const float*)d_in[1];
    float* out = (float*)d_out;

    chamfer_partial_kernel<<<NBLOCKS, TPB>>>(x, y);
    chamfer_combine_kernel<<<CBLOCKS, CTPB>>>(x, y, out);
}